// round 1
// baseline (speedup 1.0000x reference)
#include <cuda_runtime.h>

typedef unsigned long long u64;
typedef unsigned int u32;

#define T_STEPS 2048
#define NB 8
#define NH 16
#define BH (NB*NH)
#define KF 32
#define VF 64
#define KS 128
#define VS 64

// packed f32x2 helpers (Blackwell packed fp32 pipe)
__device__ __forceinline__ u64 pack2(float lo, float hi) {
    u64 r;
    asm("mov.b64 %0, {%1, %2};" : "=l"(r) : "r"(__float_as_uint(lo)), "r"(__float_as_uint(hi)));
    return r;
}
__device__ __forceinline__ void unpack2(u64 a, float& lo, float& hi) {
    u32 l, h;
    asm("mov.b64 {%0, %1}, %2;" : "=r"(l), "=r"(h) : "l"(a));
    lo = __uint_as_float(l); hi = __uint_as_float(h);
}
__device__ __forceinline__ u64 fma2_(u64 a, u64 b, u64 c) {
    u64 d; asm("fma.rn.f32x2 %0, %1, %2, %3;" : "=l"(d) : "l"(a), "l"(b), "l"(c)); return d;
}
__device__ __forceinline__ u64 mul2_(u64 a, u64 b) {
    u64 d; asm("mul.rn.f32x2 %0, %1, %2;" : "=l"(d) : "l"(a), "l"(b)); return d;
}

// smem per-step buffer (floats):
// [0,32) kf | [32,64) qf | [64,192) ks (swizzled) | [192,320) qs (swizzled)
// [320,384) vf | [384,448) vs | [448,453) scalars {df, ds, g, mf, ms} | pad to 456
#define STEP_F 456

__global__ __launch_bounds__(256, 1)
void e90_kernel(const float* __restrict__ k_fast, const float* __restrict__ v_fast,
                const float* __restrict__ q_fast, const float* __restrict__ decay_fast,
                const float* __restrict__ k_slow, const float* __restrict__ v_slow,
                const float* __restrict__ q_slow, const float* __restrict__ decay_slow,
                const float* __restrict__ slow_gate, const float* __restrict__ mix_fast,
                const float* __restrict__ mix_slow, const float* __restrict__ S_fast0,
                const float* __restrict__ S_slow0, float* __restrict__ out)
{
    __shared__ __align__(16) float smem[2 * STEP_F];

    const int tid = threadIdx.x;
    const int bh  = blockIdx.x;
    const int kg  = tid & 3;    // k-group: which quarter of the K dimension
    const int vj  = tid >> 2;   // value column 0..63

    // ---- prefetch role: each thread stages at most one 16B chunk per step ----
    const float* src = 0;
    int   smoff  = -1;
    long  stride = 0;
    bool  wide   = true;
    {
        int c = tid;
        if (c < 8)        {              src = k_fast + (size_t)bh*KF + c*4;       smoff = c*4;                               stride = (long)BH*KF; }
        else if (c < 16)  { int g = c-8;  src = q_fast + (size_t)bh*KF + g*4;      smoff = 32  + g*4;                         stride = (long)BH*KF; }
        else if (c < 48)  { int g = c-16; src = k_slow + (size_t)bh*KS + g*4;      smoff = 64  + ((g&7)*4 + (g>>3))*4;        stride = (long)BH*KS; }
        else if (c < 80)  { int g = c-48; src = q_slow + (size_t)bh*KS + g*4;      smoff = 192 + ((g&7)*4 + (g>>3))*4;        stride = (long)BH*KS; }
        else if (c < 96)  { int g = c-80; src = v_fast + (size_t)bh*VF + g*4;      smoff = 320 + g*4;                         stride = (long)BH*VF; }
        else if (c < 112) { int g = c-96; src = v_slow + (size_t)bh*VS + g*4;      smoff = 384 + g*4;                         stride = (long)BH*VS; }
        else if (c < 117) {
            const float* arrs[5] = {decay_fast, decay_slow, slow_gate, mix_fast, mix_slow};
            src = arrs[c-112] + bh; smoff = 448 + (c-112); stride = (long)BH; wide = false;
        }
    }
    const bool pv = (smoff >= 0);

    // ---- prologue: stage step 0 ----
    if (pv) {
        if (wide) { float4 p = *(const float4*)src; *(float4*)(smem + smoff) = p; }
        else      { smem[smoff] = *src; }
        src += stride;
    }

    // ---- load initial states (rows packed in pairs: reg p holds rows (base+2p, base+2p+1), column vj) ----
    u64 Sf[4], Ss[16];
    {
        const float* p0 = S_fast0 + (size_t)bh*KF*VF + vj;
        #pragma unroll
        for (int p = 0; p < 4; p++) {
            int r = kg*8 + 2*p;
            Sf[p] = pack2(p0[(size_t)r*VF], p0[(size_t)(r+1)*VF]);
        }
        const float* p1 = S_slow0 + (size_t)bh*KS*VS + vj;
        #pragma unroll
        for (int p = 0; p < 16; p++) {
            int r = kg*32 + 2*p;
            Ss[p] = pack2(p1[(size_t)r*VS], p1[(size_t)(r+1)*VS]);
        }
    }
    __syncthreads();

    // output region: [S_f_final | S_s_final | output]
    float* outO = out + (size_t)BH*(KF*VF + KS*VS) + (size_t)bh*VF + vj;
    const bool writer = (kg == 0);

    for (int t = 0; t < T_STEPS; t++) {
        const float* cur = smem + (t & 1) * STEP_F;
        float*       nxt = smem + ((t + 1) & 1) * STEP_F;

        // issue next step's global load early (latency hidden by this step's compute)
        const bool pre = pv && (t + 1 < T_STEPS);
        float4 pf;
        if (pre) {
            if (wide) pf = *(const float4*)src;
            else      pf.x = *src;
        }

        // per-step scalars (smem broadcast)
        float4 sc4 = *(const float4*)(cur + 448);
        float df = sc4.x, ds = sc4.y, g = sc4.z, mf = sc4.w;
        float ms = cur[452];
        float de = 1.0f + g * (ds - 1.0f);          // effective slow decay: g*ds + (1-g)

        float vfv = cur[320 + vj];
        float vsv = g * cur[384 + vj];              // fold gate into the slow outer-product term
        u64 vf2 = pack2(vfv, vfv);
        u64 vs2 = pack2(vsv, vsv);
        u64 df2 = pack2(df, df);
        u64 de2 = pack2(de, de);
        u64 accf = 0ull, accs = 0ull;

        // ---- fast state: 4 row-pairs ----
        {
            const ulonglong2* kp = (const ulonglong2*)(cur + 0)  + kg*2;
            const ulonglong2* qp = (const ulonglong2*)(cur + 32) + kg*2;
            #pragma unroll
            for (int j = 0; j < 2; j++) {
                ulonglong2 kk = kp[j];
                ulonglong2 qq = qp[j];
                Sf[2*j]   = fma2_(df2, Sf[2*j],   mul2_(kk.x, vf2));
                accf      = fma2_(qq.x, Sf[2*j],   accf);
                Sf[2*j+1] = fma2_(df2, Sf[2*j+1], mul2_(kk.y, vf2));
                accf      = fma2_(qq.y, Sf[2*j+1], accf);
            }
        }
        // ---- slow state: 16 row-pairs (swizzled smem: slot q*4+kg -> conflict-free) ----
        {
            const ulonglong2* kp = (const ulonglong2*)(cur + 64)  + kg;
            const ulonglong2* qp = (const ulonglong2*)(cur + 192) + kg;
            #pragma unroll
            for (int q = 0; q < 8; q++) {
                ulonglong2 kk = kp[4*q];
                ulonglong2 qq = qp[4*q];
                Ss[2*q]   = fma2_(de2, Ss[2*q],   mul2_(kk.x, vs2));
                accs      = fma2_(qq.x, Ss[2*q],   accs);
                Ss[2*q+1] = fma2_(de2, Ss[2*q+1], mul2_(kk.y, vs2));
                accs      = fma2_(qq.y, Ss[2*q+1], accs);
            }
        }

        // mix + horizontal (row-pair) add + reduce across the 4 k-groups (lanes kg=0..3)
        float flo, fhi, slo, shi;
        unpack2(accf, flo, fhi);
        unpack2(accs, slo, shi);
        float o = mf * (flo + fhi) + ms * (slo + shi);
        o += __shfl_xor_sync(0xffffffffu, o, 1);
        o += __shfl_xor_sync(0xffffffffu, o, 2);
        if (writer) *outO = o;
        outO += (size_t)BH * VF;

        // commit next step's staged data, then barrier
        if (pre) {
            if (wide) *(float4*)(nxt + smoff) = pf;
            else      nxt[smoff] = pf.x;
            src += stride;
        }
        __syncthreads();
    }

    // ---- final states ----
    {
        float* oSf = out + (size_t)bh*KF*VF + vj;
        #pragma unroll
        for (int p = 0; p < 4; p++) {
            int r = kg*8 + 2*p;
            float lo, hi; unpack2(Sf[p], lo, hi);
            oSf[(size_t)r*VF]     = lo;
            oSf[(size_t)(r+1)*VF] = hi;
        }
        float* oSs = out + (size_t)BH*KF*VF + (size_t)bh*KS*VS + vj;
        #pragma unroll
        for (int p = 0; p < 16; p++) {
            int r = kg*32 + 2*p;
            float lo, hi; unpack2(Ss[p], lo, hi);
            oSs[(size_t)r*VS]     = lo;
            oSs[(size_t)(r+1)*VS] = hi;
        }
    }
}

extern "C" void kernel_launch(void* const* d_in, const int* in_sizes, int n_in,
                              void* d_out, int out_size) {
    (void)in_sizes; (void)n_in; (void)out_size;
    e90_kernel<<<BH, 256>>>(
        (const float*)d_in[0],  (const float*)d_in[1],  (const float*)d_in[2],
        (const float*)d_in[3],  (const float*)d_in[4],  (const float*)d_in[5],
        (const float*)d_in[6],  (const float*)d_in[7],  (const float*)d_in[8],
        (const float*)d_in[9],  (const float*)d_in[10], (const float*)d_in[11],
        (const float*)d_in[12], (float*)d_out);
}